// round 9
// baseline (speedup 1.0000x reference)
#include <cuda_runtime.h>
#include <cstdint>

// RGCNHighMem: out[dst] += feat[src] @ W[etype]
// v9: v7 phase structure, 4-way column split:
//   lane (m2 = l&7, p4 = l>>3) owns edges {m2,m2+8,m2+16,m2+24},
//   output quads {p4, p4+4} (16 u64 acc).
//   A: cooperative gather, stage dup-pairs (17-f4 stride)
//   B: LDS.64 dup operands (conflict-free, zero ALU) + 2 broadcast W-LDS per i
//      feeding 16 FFMA2; 16 independent acc chains
//   C: direct red.add.v4 from acc (4 contiguous quads x 8 rows per instr)

#define RELS   64
#define EPB    256          // edges per main-kernel block (4 warps x 2 x 32)
#define SCHUNK 512          // edges per scatter block
#define CAP    8192         // per-relation bucket capacity (max expected ~3.4K)
#define MAXK   (CAP / EPB)  // 32 chunks per relation

__device__ int g_cnt[RELS];
__device__ unsigned long long g_edges[RELS * CAP];  // packed (src | dst<<32)

// Single-pass scatter + d_out zeroing.
__global__ __launch_bounds__(256)
void k_scatter(const int* __restrict__ src, const int* __restrict__ dst,
               const int* __restrict__ et, int E,
               float4* __restrict__ out4, int nout4) {
    __shared__ int cnt[RELS], base[RELS];
    int tid = threadIdx.x;

    for (int i = blockIdx.x * 256 + tid; i < nout4; i += gridDim.x * 256)
        out4[i] = make_float4(0.f, 0.f, 0.f, 0.f);

    int b0 = blockIdx.x * SCHUNK;
    int b1 = min(E, b0 + SCHUNK);
    if (tid < RELS) cnt[tid] = 0;
    __syncthreads();

    int t0 = -1, t1 = -1;
    int e0 = b0 + tid, e1 = b0 + tid + 256;
    if (e0 < b1) { t0 = et[e0]; atomicAdd(&cnt[t0], 1); }
    if (e1 < b1) { t1 = et[e1]; atomicAdd(&cnt[t1], 1); }
    __syncthreads();

    if (tid < RELS) {
        int v = cnt[tid];
        base[tid] = v ? atomicAdd(&g_cnt[tid], v) : 0;
        cnt[tid] = 0;
    }
    __syncthreads();

    if (t0 >= 0) {
        int p = base[t0] + atomicAdd(&cnt[t0], 1);
        g_edges[t0 * CAP + p] =
            (unsigned long long)(unsigned)src[e0] |
            ((unsigned long long)(unsigned)dst[e0] << 32);
    }
    if (t1 >= 0) {
        int p = base[t1] + atomicAdd(&cnt[t1], 1);
        g_edges[t1 * CAP + p] =
            (unsigned long long)(unsigned)src[e1] |
            ((unsigned long long)(unsigned)dst[e1] << 32);
    }
}

__global__ __launch_bounds__(128, 6)
void k_main(const float4* __restrict__ feat4, const float4* __restrict__ W4,
            float* __restrict__ out) {
    int r = blockIdx.x >> 5;            // MAXK = 32
    int kk = blockIdx.x & (MAXK - 1);
    int cnt = g_cnt[r];
    int segs = kk * EPB;
    if (segs >= cnt) return;            // block-uniform
    int sege = min(cnt, segs + EPB);
    const unsigned long long* eb = g_edges + (size_t)r * CAP;

    __shared__ float4 Wsh[256];              // W[r]: [32 rows][8 quads]
    // per-warp stage: 32 rows x 17 f4 (16 dup-pair f4 + pad) = 272B stride
    __shared__ float4 stage[4][32 * 17];

    int tid = threadIdx.x;
    Wsh[tid]       = W4[r * 256 + tid];
    Wsh[tid + 128] = W4[r * 256 + tid + 128];
    __syncthreads();
    const ulonglong2* Ws2 = (const ulonglong2*)Wsh;

    int w = tid >> 5, l = tid & 31;
    int m2 = l & 7, p4 = l >> 3;   // edges {m2+8j}, quads {p4, p4+4}
    float4* st = stage[w];
    const unsigned long long* stu = (const unsigned long long*)st;

    // per-edge-row dup-operand base pointers (u64 stride 34 per row)
    const unsigned long long* rw0 = stu + (m2 + 0)  * 34;
    const unsigned long long* rw1 = stu + (m2 + 8)  * 34;
    const unsigned long long* rw2 = stu + (m2 + 16) * 34;
    const unsigned long long* rw3 = stu + (m2 + 24) * 34;

    #pragma unroll 1
    for (int t = 0; t < 2; t++) {
        int e0 = segs + w * 64 + t * 32;
        if (e0 >= sege) break;

        // ---- Phase A: cooperative gather; stage dup-pairs ----
        #pragma unroll
        for (int g = 0; g < 8; g++) {
            int row = g * 4 + p4;
            int e = min(e0 + row, sege - 1);
            unsigned long long pk = eb[e];          // 8-lane dup -> 1 line
            int s = (int)(unsigned)pk;
            float4 f = feat4[s * 8 + m2];           // 4 rows per LDG.128
            st[row * 17 + m2 * 2]     = make_float4(f.x, f.x, f.y, f.y);
            st[row * 17 + m2 * 2 + 1] = make_float4(f.z, f.z, f.w, f.w);
        }
        __syncwarp();

        // ---- Phase B: 4 edges/lane, 16 f32x2 acc chains ----
        // acc[j*4 + q*2 + h]: edge j, quad (p4+4q), f32x2 half h
        unsigned long long acc[16];
        #pragma unroll
        for (int j = 0; j < 16; j++) acc[j] = 0ULL;

        #pragma unroll
        for (int i = 0; i < 32; i++) {
            ulonglong2 w0 = Ws2[i * 8 + p4];        // quad p4 (8-way bcast)
            ulonglong2 w1 = Ws2[i * 8 + p4 + 4];    // quad p4+4
            unsigned long long d0 = rw0[i];         // dup operands, LDS.64
            unsigned long long d1 = rw1[i];         // banks 4*m2: conflict-free
            unsigned long long d2 = rw2[i];
            unsigned long long d3 = rw3[i];
            asm("fma.rn.f32x2 %0, %1, %2, %0;" : "+l"(acc[0])  : "l"(d0), "l"(w0.x));
            asm("fma.rn.f32x2 %0, %1, %2, %0;" : "+l"(acc[1])  : "l"(d0), "l"(w0.y));
            asm("fma.rn.f32x2 %0, %1, %2, %0;" : "+l"(acc[2])  : "l"(d0), "l"(w1.x));
            asm("fma.rn.f32x2 %0, %1, %2, %0;" : "+l"(acc[3])  : "l"(d0), "l"(w1.y));
            asm("fma.rn.f32x2 %0, %1, %2, %0;" : "+l"(acc[4])  : "l"(d1), "l"(w0.x));
            asm("fma.rn.f32x2 %0, %1, %2, %0;" : "+l"(acc[5])  : "l"(d1), "l"(w0.y));
            asm("fma.rn.f32x2 %0, %1, %2, %0;" : "+l"(acc[6])  : "l"(d1), "l"(w1.x));
            asm("fma.rn.f32x2 %0, %1, %2, %0;" : "+l"(acc[7])  : "l"(d1), "l"(w1.y));
            asm("fma.rn.f32x2 %0, %1, %2, %0;" : "+l"(acc[8])  : "l"(d2), "l"(w0.x));
            asm("fma.rn.f32x2 %0, %1, %2, %0;" : "+l"(acc[9])  : "l"(d2), "l"(w0.y));
            asm("fma.rn.f32x2 %0, %1, %2, %0;" : "+l"(acc[10]) : "l"(d2), "l"(w1.x));
            asm("fma.rn.f32x2 %0, %1, %2, %0;" : "+l"(acc[11]) : "l"(d2), "l"(w1.y));
            asm("fma.rn.f32x2 %0, %1, %2, %0;" : "+l"(acc[12]) : "l"(d3), "l"(w0.x));
            asm("fma.rn.f32x2 %0, %1, %2, %0;" : "+l"(acc[13]) : "l"(d3), "l"(w0.y));
            asm("fma.rn.f32x2 %0, %1, %2, %0;" : "+l"(acc[14]) : "l"(d3), "l"(w1.x));
            asm("fma.rn.f32x2 %0, %1, %2, %0;" : "+l"(acc[15]) : "l"(d3), "l"(w1.y));
        }
        __syncwarp();   // stage reads done before next tile's Phase A

        // ---- Phase C: direct cooperative scatter from acc ----
        #pragma unroll
        for (int j = 0; j < 4; j++) {
            int e = e0 + m2 + 8 * j;
            if (e < sege) {
                unsigned long long pk = eb[e];      // L1 hit, 8-addr
                int d = (int)(pk >> 32);
                float* pr = out + (size_t)d * 32;
                #pragma unroll
                for (int q = 0; q < 2; q++) {
                    unsigned x, y, z, u;
                    asm("mov.b64 {%0,%1}, %2;" : "=r"(x), "=r"(y)
                        : "l"(acc[j * 4 + q * 2]));
                    asm("mov.b64 {%0,%1}, %2;" : "=r"(z), "=r"(u)
                        : "l"(acc[j * 4 + q * 2 + 1]));
                    // quad (p4 + 4q): instr covers 4 contiguous quads x 8 rows
                    asm volatile("red.global.add.v4.f32 [%0], {%1,%2,%3,%4};"
                                 :: "l"(pr + (p4 + 4 * q) * 4),
                                    "f"(__uint_as_float(x)), "f"(__uint_as_float(y)),
                                    "f"(__uint_as_float(z)), "f"(__uint_as_float(u))
                                 : "memory");
                }
            }
        }
    }
}

extern "C" void kernel_launch(void* const* d_in, const int* in_sizes, int n_in,
                              void* d_out, int out_size) {
    const float* feat = (const float*)d_in[0];
    const float* W    = (const float*)d_in[1];
    const int*   src  = (const int*)d_in[2];
    const int*   dst  = (const int*)d_in[3];
    const int*   et   = (const int*)d_in[4];
    int E = in_sizes[2];

    void* cnt_addr = nullptr;
    cudaGetSymbolAddress(&cnt_addr, g_cnt);

    cudaMemsetAsync(cnt_addr, 0, RELS * sizeof(int), 0);
    k_scatter<<<(E + SCHUNK - 1) / SCHUNK, 256>>>(src, dst, et, E,
                                                  (float4*)d_out, out_size / 4);
    k_main<<<RELS * MAXK, 128>>>((const float4*)feat, (const float4*)W,
                                 (float*)d_out);
}

// round 10
// speedup vs baseline: 1.1248x; 1.1248x over previous
#include <cuda_runtime.h>
#include <cstdint>

// RGCNHighMem: out[dst] += feat[src] @ W[etype]
// v10: v7 phase structure + 4-way column split + TRANSPOSED dup stage:
//   stage[i][row] (stride 33 u64) so Phase B reads FFMA2-ready dup operands
//   via conflict-free LDS.64 with zero movs; fits occ 6 (37.9KB smem).
//   lane (m2 = l&7, p4 = l>>3): edges {m2+8j}, output quads {p4, p4+4}.
//   A: cooperative gather (4 rows/LDG.128), dup STS.64 writes (all-32-bank)
//   B: per i: 4 LDS.64 + 2 broadcast W-LDS.128 + 16 FFMA2 (16 indep chains)
//   C: direct red.add.v4 from acc (2 instrs cover 8 edges fully)

#define RELS   64
#define EPB    256          // edges per main-kernel block (4 warps x 2 x 32)
#define SCHUNK 512          // edges per scatter block
#define CAP    8192         // per-relation bucket capacity (max expected ~3.4K)
#define MAXK   (CAP / EPB)  // 32 chunks per relation

__device__ int g_cnt[RELS];
__device__ unsigned long long g_edges[RELS * CAP];  // packed (src | dst<<32)

// Single-pass scatter + d_out zeroing.
__global__ __launch_bounds__(256)
void k_scatter(const int* __restrict__ src, const int* __restrict__ dst,
               const int* __restrict__ et, int E,
               float4* __restrict__ out4, int nout4) {
    __shared__ int cnt[RELS], base[RELS];
    int tid = threadIdx.x;

    for (int i = blockIdx.x * 256 + tid; i < nout4; i += gridDim.x * 256)
        out4[i] = make_float4(0.f, 0.f, 0.f, 0.f);

    int b0 = blockIdx.x * SCHUNK;
    int b1 = min(E, b0 + SCHUNK);
    if (tid < RELS) cnt[tid] = 0;
    __syncthreads();

    int t0 = -1, t1 = -1;
    int e0 = b0 + tid, e1 = b0 + tid + 256;
    if (e0 < b1) { t0 = et[e0]; atomicAdd(&cnt[t0], 1); }
    if (e1 < b1) { t1 = et[e1]; atomicAdd(&cnt[t1], 1); }
    __syncthreads();

    if (tid < RELS) {
        int v = cnt[tid];
        base[tid] = v ? atomicAdd(&g_cnt[tid], v) : 0;
        cnt[tid] = 0;
    }
    __syncthreads();

    if (t0 >= 0) {
        int p = base[t0] + atomicAdd(&cnt[t0], 1);
        g_edges[t0 * CAP + p] =
            (unsigned long long)(unsigned)src[e0] |
            ((unsigned long long)(unsigned)dst[e0] << 32);
    }
    if (t1 >= 0) {
        int p = base[t1] + atomicAdd(&cnt[t1], 1);
        g_edges[t1 * CAP + p] =
            (unsigned long long)(unsigned)src[e1] |
            ((unsigned long long)(unsigned)dst[e1] << 32);
    }
}

#define ISTRIDE 33   // u64 stride per input-dim i in the stage

__global__ __launch_bounds__(128, 6)
void k_main(const float4* __restrict__ feat4, const float4* __restrict__ W4,
            float* __restrict__ out) {
    int r = blockIdx.x >> 5;            // MAXK = 32
    int kk = blockIdx.x & (MAXK - 1);
    int cnt = g_cnt[r];
    int segs = kk * EPB;
    if (segs >= cnt) return;            // block-uniform
    int sege = min(cnt, segs + EPB);
    const unsigned long long* eb = g_edges + (size_t)r * CAP;

    __shared__ float4 Wsh[256];                       // W[r]: [32 rows][8 quads]
    // transposed dup stage: [warp][i=0..31][row=0..31], stride ISTRIDE u64
    __shared__ unsigned long long stage[4][32 * ISTRIDE];

    int tid = threadIdx.x;
    Wsh[tid]       = W4[r * 256 + tid];
    Wsh[tid + 128] = W4[r * 256 + tid + 128];
    __syncthreads();
    const ulonglong2* Ws2 = (const ulonglong2*)Wsh;

    int w = tid >> 5, l = tid & 31;
    int m2 = l & 7, p4 = l >> 3;        // edges {m2+8j}, quads {p4, p4+4}
    unsigned long long* st = stage[w];

    // Phase A write base: i = 4*m2 + k  ->  st[(4*m2+k)*ISTRIDE + row]
    unsigned long long* wr = st + (4 * m2) * ISTRIDE;
    // Phase B read bases: rows m2 + 8j at dim i -> st[i*ISTRIDE + m2 + 8j]
    const unsigned long long* rd = st + m2;

    #pragma unroll 1
    for (int t = 0; t < 2; t++) {
        int e0 = segs + w * 64 + t * 32;
        if (e0 >= sege) break;

        // ---- Phase A: cooperative gather; transposed dup STS.64 ----
        #pragma unroll
        for (int g = 0; g < 8; g++) {
            int row = g * 4 + p4;
            int e = min(e0 + row, sege - 1);
            unsigned long long pk = eb[e];          // 8-lane dup -> 1 line
            int s = (int)(unsigned)pk;
            float4 f = feat4[s * 8 + m2];           // 4 rows per LDG.128
            unsigned long long dx, dy, dz, dw;
            asm("mov.b64 %0, {%1, %1};" : "=l"(dx) : "r"(__float_as_uint(f.x)));
            asm("mov.b64 %0, {%1, %1};" : "=l"(dy) : "r"(__float_as_uint(f.y)));
            asm("mov.b64 %0, {%1, %1};" : "=l"(dz) : "r"(__float_as_uint(f.z)));
            asm("mov.b64 %0, {%1, %1};" : "=l"(dw) : "r"(__float_as_uint(f.w)));
            wr[0 * ISTRIDE + row] = dx;   // banks: 8m2+2k+8g+2p4 -> all 32
            wr[1 * ISTRIDE + row] = dy;
            wr[2 * ISTRIDE + row] = dz;
            wr[3 * ISTRIDE + row] = dw;
        }
        __syncwarp();

        // ---- Phase B: 4 edges/lane, 16 f32x2 acc chains ----
        // acc[j*4 + q*2 + h]: edge (m2+8j), quad (p4+4q), f32x2 half h
        unsigned long long acc[16];
        #pragma unroll
        for (int j = 0; j < 16; j++) acc[j] = 0ULL;

        #pragma unroll
        for (int i = 0; i < 32; i++) {
            ulonglong2 w0 = Ws2[i * 8 + p4];        // quad p4 (8-way bcast)
            ulonglong2 w1 = Ws2[i * 8 + p4 + 4];    // quad p4+4
            const unsigned long long* ri = rd + i * ISTRIDE;
            unsigned long long d0 = ri[0];          // LDS.64, conflict-free
            unsigned long long d1 = ri[8];
            unsigned long long d2 = ri[16];
            unsigned long long d3 = ri[24];
            asm("fma.rn.f32x2 %0, %1, %2, %0;" : "+l"(acc[0])  : "l"(d0), "l"(w0.x));
            asm("fma.rn.f32x2 %0, %1, %2, %0;" : "+l"(acc[1])  : "l"(d0), "l"(w0.y));
            asm("fma.rn.f32x2 %0, %1, %2, %0;" : "+l"(acc[2])  : "l"(d0), "l"(w1.x));
            asm("fma.rn.f32x2 %0, %1, %2, %0;" : "+l"(acc[3])  : "l"(d0), "l"(w1.y));
            asm("fma.rn.f32x2 %0, %1, %2, %0;" : "+l"(acc[4])  : "l"(d1), "l"(w0.x));
            asm("fma.rn.f32x2 %0, %1, %2, %0;" : "+l"(acc[5])  : "l"(d1), "l"(w0.y));
            asm("fma.rn.f32x2 %0, %1, %2, %0;" : "+l"(acc[6])  : "l"(d1), "l"(w1.x));
            asm("fma.rn.f32x2 %0, %1, %2, %0;" : "+l"(acc[7])  : "l"(d1), "l"(w1.y));
            asm("fma.rn.f32x2 %0, %1, %2, %0;" : "+l"(acc[8])  : "l"(d2), "l"(w0.x));
            asm("fma.rn.f32x2 %0, %1, %2, %0;" : "+l"(acc[9])  : "l"(d2), "l"(w0.y));
            asm("fma.rn.f32x2 %0, %1, %2, %0;" : "+l"(acc[10]) : "l"(d2), "l"(w1.x));
            asm("fma.rn.f32x2 %0, %1, %2, %0;" : "+l"(acc[11]) : "l"(d2), "l"(w1.y));
            asm("fma.rn.f32x2 %0, %1, %2, %0;" : "+l"(acc[12]) : "l"(d3), "l"(w0.x));
            asm("fma.rn.f32x2 %0, %1, %2, %0;" : "+l"(acc[13]) : "l"(d3), "l"(w0.y));
            asm("fma.rn.f32x2 %0, %1, %2, %0;" : "+l"(acc[14]) : "l"(d3), "l"(w1.x));
            asm("fma.rn.f32x2 %0, %1, %2, %0;" : "+l"(acc[15]) : "l"(d3), "l"(w1.y));
        }
        __syncwarp();   // stage reads done before next tile's Phase A

        // ---- Phase C: direct cooperative scatter from acc ----
        #pragma unroll
        for (int j = 0; j < 4; j++) {
            int e = e0 + m2 + 8 * j;
            if (e < sege) {
                unsigned long long pk = eb[e];      // L1 hit, 8-addr
                int d = (int)(pk >> 32);
                float* pr = out + (size_t)d * 32;
                #pragma unroll
                for (int q = 0; q < 2; q++) {
                    unsigned x, y, z, u;
                    asm("mov.b64 {%0,%1}, %2;" : "=r"(x), "=r"(y)
                        : "l"(acc[j * 4 + q * 2]));
                    asm("mov.b64 {%0,%1}, %2;" : "=r"(z), "=r"(u)
                        : "l"(acc[j * 4 + q * 2 + 1]));
                    // quad (p4+4q): instr covers 8 edges x 4 contiguous quads
                    asm volatile("red.global.add.v4.f32 [%0], {%1,%2,%3,%4};"
                                 :: "l"(pr + (p4 + 4 * q) * 4),
                                    "f"(__uint_as_float(x)), "f"(__uint_as_float(y)),
                                    "f"(__uint_as_float(z)), "f"(__uint_as_float(u))
                                 : "memory");
                }
            }
        }
    }
}

extern "C" void kernel_launch(void* const* d_in, const int* in_sizes, int n_in,
                              void* d_out, int out_size) {
    const float* feat = (const float*)d_in[0];
    const float* W    = (const float*)d_in[1];
    const int*   src  = (const int*)d_in[2];
    const int*   dst  = (const int*)d_in[3];
    const int*   et   = (const int*)d_in[4];
    int E = in_sizes[2];

    void* cnt_addr = nullptr;
    cudaGetSymbolAddress(&cnt_addr, g_cnt);

    cudaMemsetAsync(cnt_addr, 0, RELS * sizeof(int), 0);
    k_scatter<<<(E + SCHUNK - 1) / SCHUNK, 256>>>(src, dst, et, E,
                                                  (float4*)d_out, out_size / 4);
    k_main<<<RELS * MAXK, 128>>>((const float4*)feat, (const float4*)W,
                                 (float*)d_out);
}

// round 12
// speedup vs baseline: 1.3904x; 1.2361x over previous
#include <cuda_runtime.h>
#include <cstdint>

// RGCNHighMem: out[dst] += feat[src] @ W[etype]
// v12: v7 compute core + pipelined gather:
//   - pk records preloaded to smem once per block (coalesced)
//   - feat gather via cp.async.cg into double-buffered per-warp stages;
//     tile t+1's gather issued before tile t's compute (latency hidden)
//   - Phase B/C identical to v7 (best measured scalar core)
// lane (m = l&15, p = l>>4): edges {m, m+16}, cols 16p..16p+15.

#define RELS   64
#define EPB    256          // edges per main-kernel block (4 warps x 2 x 32)
#define SCHUNK 512          // edges per scatter block
#define CAP    8192         // per-relation bucket capacity (max expected ~3.4K)
#define MAXK   (CAP / EPB)  // 32 chunks per relation

__device__ int g_cnt[RELS];
__device__ unsigned long long g_edges[RELS * CAP];  // packed (src | dst<<32)

__device__ __forceinline__ uint32_t smem_u32(const void* p) {
    uint32_t a;
    asm("{ .reg .u64 t; cvta.to.shared.u64 t, %1; cvt.u32.u64 %0, t; }"
        : "=r"(a) : "l"(p));
    return a;
}

// Single-pass scatter + d_out zeroing.
__global__ __launch_bounds__(256)
void k_scatter(const int* __restrict__ src, const int* __restrict__ dst,
               const int* __restrict__ et, int E,
               float4* __restrict__ out4, int nout4) {
    __shared__ int cnt[RELS], base[RELS];
    int tid = threadIdx.x;

    for (int i = blockIdx.x * 256 + tid; i < nout4; i += gridDim.x * 256)
        out4[i] = make_float4(0.f, 0.f, 0.f, 0.f);

    int b0 = blockIdx.x * SCHUNK;
    int b1 = min(E, b0 + SCHUNK);
    if (tid < RELS) cnt[tid] = 0;
    __syncthreads();

    int t0 = -1, t1 = -1;
    int e0 = b0 + tid, e1 = b0 + tid + 256;
    if (e0 < b1) { t0 = et[e0]; atomicAdd(&cnt[t0], 1); }
    if (e1 < b1) { t1 = et[e1]; atomicAdd(&cnt[t1], 1); }
    __syncthreads();

    if (tid < RELS) {
        int v = cnt[tid];
        base[tid] = v ? atomicAdd(&g_cnt[tid], v) : 0;
        cnt[tid] = 0;
    }
    __syncthreads();

    if (t0 >= 0) {
        int p = base[t0] + atomicAdd(&cnt[t0], 1);
        g_edges[t0 * CAP + p] =
            (unsigned long long)(unsigned)src[e0] |
            ((unsigned long long)(unsigned)dst[e0] << 32);
    }
    if (t1 >= 0) {
        int p = base[t1] + atomicAdd(&cnt[t1], 1);
        g_edges[t1 * CAP + p] =
            (unsigned long long)(unsigned)src[e1] |
            ((unsigned long long)(unsigned)dst[e1] << 32);
    }
}

__global__ __launch_bounds__(128, 5)
void k_main(const float4* __restrict__ feat4, const float4* __restrict__ W4,
            float* __restrict__ out) {
    int r = blockIdx.x >> 5;            // MAXK = 32
    int kk = blockIdx.x & (MAXK - 1);
    int cnt = g_cnt[r];
    int segs = kk * EPB;
    if (segs >= cnt) return;            // block-uniform
    int sege = min(cnt, segs + EPB);
    const unsigned long long* eb = g_edges + (size_t)r * CAP;

    __shared__ float4 Wsh[256];                    // W[r]: [32 rows][8 quads]
    __shared__ float4 stage[4][2][32 * 9];         // per-warp double buffer
    __shared__ unsigned long long pkst[EPB];       // preloaded edge records

    int tid = threadIdx.x;
    int nwork = sege - segs;
    Wsh[tid]       = W4[r * 256 + tid];
    Wsh[tid + 128] = W4[r * 256 + tid + 128];
    // preload pk records (coalesced; clamp tail to a valid edge)
    #pragma unroll
    for (int i = tid; i < EPB; i += 128)
        pkst[i] = eb[min(segs + i, sege - 1) ];
    __syncthreads();
    const ulonglong2* Ws2 = (const ulonglong2*)Wsh;

    int w = tid >> 5, l = tid & 31;
    int m = l & 15, p = l >> 4;          // edges {m, m+16}, cols 16p..16p+15
    int eh4 = l >> 3, c = l & 7;         // cooperative phases
    const ulonglong2* WsP = Ws2 + p * 4;

    int base_w = w * 64;                 // warp-local edge offset within chunk
    bool has0 = base_w < nwork;
    bool has1 = base_w + 32 < nwork;
    if (!has0) return;                   // no block-wide syncs remain

    // ---- issue gather for a tile into buffer b via cp.async ----
    auto issue_tile = [&](int tbase, int b) {
        uint32_t dstb = smem_u32(&stage[w][b][0]);
        #pragma unroll
        for (int g = 0; g < 8; g++) {
            int row = g * 4 + eh4;
            int idx = min(tbase + row, nwork - 1);
            unsigned long long pk = pkst[idx];       // LDS.64, 8-lane dup
            int s = (int)(unsigned)pk;
            const float4* gp = feat4 + s * 8 + c;    // 4 rows per 128B line
            uint32_t dp = dstb + (row * 9 + c) * 16;
            asm volatile("cp.async.cg.shared.global [%0], [%1], 16;"
                         :: "r"(dp), "l"(gp) : "memory");
        }
        asm volatile("cp.async.commit_group;" ::: "memory");
    };

    issue_tile(base_w, 0);
    if (has1) {
        issue_tile(base_w + 32, 1);
        asm volatile("cp.async.wait_group 1;" ::: "memory");
    } else {
        asm volatile("cp.async.wait_group 0;" ::: "memory");
    }
    __syncwarp();

    #pragma unroll 1
    for (int t = 0; t < 2; t++) {
        if (t == 1) {
            if (!has1) break;
            asm volatile("cp.async.wait_group 0;" ::: "memory");
            __syncwarp();
        }
        int tbase = base_w + t * 32;
        float4* st = stage[w][t];

        // ---- Phase B: edges m, m+16; 16 f32x2 acc chains (v7 core) ----
        unsigned long long aA[8], aB[8];
        #pragma unroll
        for (int j = 0; j < 8; j++) { aA[j] = 0ULL; aB[j] = 0ULL; }

        const ulonglong2* rowA = (const ulonglong2*)(st + m * 9);
        const ulonglong2* rowB = (const ulonglong2*)(st + (m + 16) * 9);

        #pragma unroll
        for (int q = 0; q < 8; q++) {
            ulonglong2 fqA = rowA[q];
            ulonglong2 fqB = rowB[q];
            #pragma unroll
            for (int tt = 0; tt < 4; tt++) {
                int i = 4 * q + tt;
                unsigned lo, hi, sa, sb;
                unsigned long long srcA = (tt < 2) ? fqA.x : fqA.y;
                asm("mov.b64 {%0,%1}, %2;" : "=r"(lo), "=r"(hi) : "l"(srcA));
                sa = (tt & 1) ? hi : lo;
                unsigned long long srcB = (tt < 2) ? fqB.x : fqB.y;
                asm("mov.b64 {%0,%1}, %2;" : "=r"(lo), "=r"(hi) : "l"(srcB));
                sb = (tt & 1) ? hi : lo;
                unsigned long long dA, dB;
                asm("mov.b64 %0, {%1, %1};" : "=l"(dA) : "r"(sa));
                asm("mov.b64 %0, {%1, %1};" : "=l"(dB) : "r"(sb));
                #pragma unroll
                for (int hh = 0; hh < 4; hh++) {
                    ulonglong2 wv = WsP[i * 8 + hh];  // 2-addr broadcast LDS
                    asm("fma.rn.f32x2 %0, %1, %2, %0;"
                        : "+l"(aA[2 * hh]) : "l"(dA), "l"(wv.x));
                    asm("fma.rn.f32x2 %0, %1, %2, %0;"
                        : "+l"(aA[2 * hh + 1]) : "l"(dA), "l"(wv.y));
                    asm("fma.rn.f32x2 %0, %1, %2, %0;"
                        : "+l"(aB[2 * hh]) : "l"(dB), "l"(wv.x));
                    asm("fma.rn.f32x2 %0, %1, %2, %0;"
                        : "+l"(aB[2 * hh + 1]) : "l"(dB), "l"(wv.y));
                }
            }
        }

        // Store acc quads back to stage rows m, m+16 (v7 core).
        #pragma unroll
        for (int hh = 0; hh < 4; hh++) {
            unsigned x, y, z, u;
            asm("mov.b64 {%0,%1}, %2;" : "=r"(x), "=r"(y) : "l"(aA[2 * hh]));
            asm("mov.b64 {%0,%1}, %2;" : "=r"(z), "=r"(u) : "l"(aA[2 * hh + 1]));
            st[m * 9 + p * 4 + hh] =
                make_float4(__uint_as_float(x), __uint_as_float(y),
                            __uint_as_float(z), __uint_as_float(u));
            asm("mov.b64 {%0,%1}, %2;" : "=r"(x), "=r"(y) : "l"(aB[2 * hh]));
            asm("mov.b64 {%0,%1}, %2;" : "=r"(z), "=r"(u) : "l"(aB[2 * hh + 1]));
            st[(m + 16) * 9 + p * 4 + hh] =
                make_float4(__uint_as_float(x), __uint_as_float(y),
                            __uint_as_float(z), __uint_as_float(u));
        }
        __syncwarp();

        // ---- Phase C: cooperative scatter, dst from pkst ----
        #pragma unroll
        for (int g = 0; g < 8; g++) {
            int row = g * 4 + eh4;
            int idx = tbase + row;
            if (idx < nwork) {
                unsigned long long pk = pkst[idx];   // LDS.64
                int d = (int)(pk >> 32);
                float4 a = st[row * 9 + c];
                float* pp = out + (size_t)d * 32 + c * 4;
                asm volatile("red.global.add.v4.f32 [%0], {%1,%2,%3,%4};"
                             :: "l"(pp), "f"(a.x), "f"(a.y), "f"(a.z), "f"(a.w)
                             : "memory");
            }
        }
    }
}

extern "C" void kernel_launch(void* const* d_in, const int* in_sizes, int n_in,
                              void* d_out, int out_size) {
    const float* feat = (const float*)d_in[0];
    const float* W    = (const float*)d_in[1];
    const int*   src  = (const int*)d_in[2];
    const int*   dst  = (const int*)d_in[3];
    const int*   et   = (const int*)d_in[4];
    int E = in_sizes[2];

    void* cnt_addr = nullptr;
    cudaGetSymbolAddress(&cnt_addr, g_cnt);

    cudaMemsetAsync(cnt_addr, 0, RELS * sizeof(int), 0);
    k_scatter<<<(E + SCHUNK - 1) / SCHUNK, 256>>>(src, dst, et, E,
                                                  (float4*)d_out, out_size / 4);
    k_main<<<RELS * MAXK, 128>>>((const float4*)feat, (const float4*)W,
                                 (float*)d_out);
}